// round 16
// baseline (speedup 1.0000x reference)
#include <cuda_runtime.h>
#include <cuda_bf16.h>
#include <cuda_fp16.h>
#include <cstdint>

#define EE   2048
#define CC   64
#define FF   18
#define NTOK 18432
#define KS   64
#define KCH  8       // split-K chunks in wgemm

typedef unsigned long long u64;
typedef unsigned int u32;

// Scratch (__device__ globals: allocation-free rule)
__device__ float g_part[KCH * CC * EE];                   // wgemm split-K partials (4 MB)
__device__ float g_T1[CC * EE];                           // Wmp @ Wo
__device__ __align__(16) float g_beta[CC];
__device__ __align__(16) unsigned char g_Bh[CC * EE * 2]; // M (fp16), pre-swizzled tiles

// ---------------- helpers ----------------
__device__ __forceinline__ unsigned smem_u32(const void* p) {
    return (unsigned)__cvta_generic_to_shared(p);
}
__device__ __forceinline__ void cp16(unsigned s, const void* g) {
    asm volatile("cp.async.ca.shared.global [%0], [%1], 16;" :: "r"(s), "l"(g));
}
__device__ __forceinline__ void cp_commit() { asm volatile("cp.async.commit_group;"); }
__device__ __forceinline__ void cp_wait0()  { asm volatile("cp.async.wait_group 0;"); }
__device__ __forceinline__ void sts64(u32 a, u32 lo, u32 hi) {
    asm volatile("st.shared.v2.u32 [%0], {%1,%2};" :: "r"(a), "r"(lo), "r"(hi));
}
__device__ __forceinline__ void ldsm4(u32& r0, u32& r1, u32& r2, u32& r3, u32 a) {
    asm volatile("ldmatrix.sync.aligned.m8n8.x4.shared.b16 {%0,%1,%2,%3}, [%4];"
                 : "=r"(r0), "=r"(r1), "=r"(r2), "=r"(r3) : "r"(a));
}
__device__ __forceinline__ void ldsm4t(u32& r0, u32& r1, u32& r2, u32& r3, u32 a) {
    asm volatile("ldmatrix.sync.aligned.m8n8.x4.trans.shared.b16 {%0,%1,%2,%3}, [%4];"
                 : "=r"(r0), "=r"(r1), "=r"(r2), "=r"(r3) : "r"(a));
}
__device__ __forceinline__ void mma16816(float* c, u32 a0, u32 a1, u32 a2, u32 a3,
                                         u32 b0, u32 b1) {
    asm volatile("mma.sync.aligned.m16n8k16.row.col.f32.bf16.bf16.f32 "
                 "{%0,%1,%2,%3}, {%4,%5,%6,%7}, {%8,%9}, {%0,%1,%2,%3};"
                 : "+f"(c[0]), "+f"(c[1]), "+f"(c[2]), "+f"(c[3])
                 : "r"(a0), "r"(a1), "r"(a2), "r"(a3), "r"(b0), "r"(b1));
}
__device__ __forceinline__ void mma16816h(float* c, u32 a0, u32 a1, u32 a2, u32 a3,
                                          u32 b0, u32 b1) {
    asm volatile("mma.sync.aligned.m16n8k16.row.col.f32.f16.f16.f32 "
                 "{%0,%1,%2,%3}, {%4,%5,%6,%7}, {%8,%9}, {%0,%1,%2,%3};"
                 : "+f"(c[0]), "+f"(c[1]), "+f"(c[2]), "+f"(c[3])
                 : "r"(a0), "r"(a1), "r"(a2), "r"(a3), "r"(b0), "r"(b1));
}
__device__ __forceinline__ u32 swz(u32 off) { return off ^ ((off >> 3) & 0x70u); }

__device__ __forceinline__ void split4(float4 v, u32& h01, u32& h23, u32& l01, u32& l23) {
    asm("cvt.rn.bf16x2.f32 %0, %1, %2;" : "=r"(h01) : "f"(v.y), "f"(v.x));
    asm("cvt.rn.bf16x2.f32 %0, %1, %2;" : "=r"(h23) : "f"(v.w), "f"(v.z));
    float e0 = v.x - __uint_as_float(h01 << 16);
    float e1 = v.y - __uint_as_float(h01 & 0xffff0000u);
    float e2 = v.z - __uint_as_float(h23 << 16);
    float e3 = v.w - __uint_as_float(h23 & 0xffff0000u);
    asm("cvt.rn.bf16x2.f32 %0, %1, %2;" : "=r"(l01) : "f"(e1), "f"(e0));
    asm("cvt.rn.bf16x2.f32 %0, %1, %2;" : "=r"(l23) : "f"(e3), "f"(e2));
}

// ---------------------------------------------------------------------------
// wgemm (split-K, bf16 3-term) — unchanged (proven; keeps M accurate in fp32).
// ---------------------------------------------------------------------------
__global__ void __launch_bounds__(256, 2)
wgemm(const float* __restrict__ Aglob, const float* __restrict__ Bglob, int useT1)
{
    const float* A = useT1 ? g_T1 : Aglob;
    extern __shared__ char smraw[];
    const u32 base = (smem_u32(smraw) + 1023u) & ~1023u;
    const u32 AH[2]  = { base,          base + 8192u  };
    const u32 AL[2]  = { base + 16384u, base + 24576u };
    const u32 BSH[2] = { base + 32768u, base + 40960u };
    const u32 BSL[2] = { base + 49152u, base + 57344u };

    const int tid = threadIdx.x;
    const int wid = tid >> 5, lane = tid & 31;
    const int j0 = blockIdx.x * 64;
    const int kbase = blockIdx.y * 256;
    const int c0 = (wid & 3) * 16;
    const int jh = (wid >> 2) * 32;

    const int lr = tid >> 4;
    const int lc = tid & 15;

    float acc[4][4];
#pragma unroll
    for (int i = 0; i < 4; ++i)
#pragma unroll
        for (int j = 0; j < 4; ++j) acc[i][j] = 0.f;

    float4 rA[4], rB[4];
#pragma unroll
    for (int i = 0; i < 4; ++i) {
        rA[i] = *(const float4*)(A + (size_t)(lr + 16 * i) * EE + kbase + lc * 4);
        rB[i] = *(const float4*)(Bglob + (size_t)(kbase + lr + 16 * i) * EE + j0 + lc * 4);
    }

    for (int t = 0; t < 4; ++t) {
        const int buf = t & 1;
#pragma unroll
        for (int i = 0; i < 4; ++i) {
            const u32 sw = swz((u32)((lr + 16 * i) * 128 + lc * 8));
            u32 h01, h23, l01, l23;
            split4(rA[i], h01, h23, l01, l23);
            sts64(AH[buf] + sw, h01, h23);
            sts64(AL[buf] + sw, l01, l23);
            split4(rB[i], h01, h23, l01, l23);
            sts64(BSH[buf] + sw, h01, h23);
            sts64(BSL[buf] + sw, l01, l23);
        }
        __syncthreads();

        if (t + 1 < 4) {
            const int kc = kbase + (t + 1) * 64;
#pragma unroll
            for (int i = 0; i < 4; ++i) {
                rA[i] = *(const float4*)(A + (size_t)(lr + 16 * i) * EE + kc + lc * 4);
                rB[i] = *(const float4*)(Bglob + (size_t)(kc + lr + 16 * i) * EE + j0 + lc * 4);
            }
        }

        const int r = lane & 7, g = lane >> 3;
#pragma unroll
        for (int s = 0; s < 4; ++s) {
            const u32 asw = swz((u32)((c0 + (lane & 15)) * 128 + s * 32 + (lane >> 4) * 16));
            u32 a0, a1, a2, a3, f0, f1, f2, f3;
            ldsm4(a0, a1, a2, a3, AH[buf] + asw);
            ldsm4(f0, f1, f2, f3, AL[buf] + asw);
#pragma unroll
            for (int h = 0; h < 2; ++h) {
                const int jb = jh + h * 16;
                const u32 bsw = swz((u32)((s * 16 + (g >> 1) * 8 + r) * 128
                                          + (jb + (g & 1) * 8) * 2));
                u32 b0, b1, b2, b3, e0, e1, e2, e3;
                ldsm4t(b0, b1, b2, b3, BSH[buf] + bsw);
                ldsm4t(e0, e1, e2, e3, BSL[buf] + bsw);
                mma16816(acc[2 * h],     a0, a1, a2, a3, b0, b2);
                mma16816(acc[2 * h],     a0, a1, a2, a3, e0, e2);
                mma16816(acc[2 * h],     f0, f1, f2, f3, b0, b2);
                mma16816(acc[2 * h + 1], a0, a1, a2, a3, b1, b3);
                mma16816(acc[2 * h + 1], a0, a1, a2, a3, e1, e3);
                mma16816(acc[2 * h + 1], f0, f1, f2, f3, b1, b3);
            }
        }
        if (t + 1 < 4) __syncthreads();
    }

    const int r0 = lane >> 2;
    const int cb = 2 * (lane & 3);
    float* pbase = g_part + (size_t)blockIdx.y * (CC * EE);
#pragma unroll
    for (int nt = 0; nt < 4; ++nt) {
        const int j = j0 + jh + nt * 8 + cb;
        const int ca = c0 + r0, cbig = ca + 8;
        *(float2*)&pbase[(size_t)ca * EE + j]   = make_float2(acc[nt][0], acc[nt][1]);
        *(float2*)&pbase[(size_t)cbig * EE + j] = make_float2(acc[nt][2], acc[nt][3]);
    }
}

// ---------------------------------------------------------------------------
// reduceK: blocks 0..127 sum KCH split-K partials (float4 per thread).
//   which==0 -> g_T1 (fp32)
//   which==1 -> 0.75x, single fp16, pre-swizzled tiles.
// Mode 1 blocks 128..191: beta[c] = 0.75*(T1[c,:]@bv + Wmp[c,:]@bo) + bmp[c]
// ---------------------------------------------------------------------------
__global__ void reduceK(int which, const float* __restrict__ bv,
                        const float* __restrict__ bo, const float* __restrict__ bmp,
                        const float* __restrict__ Wmp)
{
    const int tid = threadIdx.x;
    if (blockIdx.x >= 128) {            // beta blocks (mode 1 only)
        __shared__ float red[256];
        const int c = blockIdx.x - 128;
        const float4* t1r = (const float4*)(g_T1 + (size_t)c * EE);
        const float4* wmr = (const float4*)(Wmp + (size_t)c * EE);
        const float4* bv4 = (const float4*)bv;
        const float4* bo4 = (const float4*)bo;
        float s = 0.f;
#pragma unroll
        for (int q = 0; q < 2; ++q) {
            const int i = tid + 256 * q;
            float4 a = t1r[i], b = bv4[i], d = wmr[i], e = bo4[i];
            s += a.x * b.x + a.y * b.y + a.z * b.z + a.w * b.w;
            s += d.x * e.x + d.y * e.y + d.z * e.z + d.w * e.w;
        }
        red[tid] = s;
        __syncthreads();
#pragma unroll
        for (int o = 128; o >= 32; o >>= 1) {
            if (tid < o) red[tid] += red[tid + o];
            __syncthreads();
        }
        if (tid < 32) {
            float v = red[tid];
#pragma unroll
            for (int o = 16; o; o >>= 1) v += __shfl_xor_sync(0xffffffffu, v, o);
            if (tid == 0) g_beta[c] = 0.75f * v + bmp[c];
        }
        return;
    }

    const int i4 = blockIdx.x * 256 + tid;  // 0 .. 32767
    float4 s = make_float4(0.f, 0.f, 0.f, 0.f);
#pragma unroll
    for (int q = 0; q < KCH; ++q) {
        float4 v = *(const float4*)&g_part[(size_t)q * (CC * EE) + i4 * 4];
        s.x += v.x; s.y += v.y; s.z += v.z; s.w += v.w;
    }
    if (which == 0) {
        *(float4*)&g_T1[i4 * 4] = s;
    } else {
        s.x *= 0.75f; s.y *= 0.75f; s.z *= 0.75f; s.w *= 0.75f;
        __half2 H01 = __floats2half2_rn(s.x, s.y);
        __half2 H23 = __floats2half2_rn(s.z, s.w);
        const int i = i4 * 4;
        const int c = i >> 11, k = i & 2047;
        const int stage = k >> 6, kk = k & 63;
        const u32 sw = swz((u32)(c * 128 + kk * 2));
        *(u32*)(g_Bh + (size_t)stage * 8192 + sw)     = *(u32*)&H01;
        *(u32*)(g_Bh + (size_t)stage * 8192 + sw + 4) = *(u32*)&H23;
    }
}

// ---------------------------------------------------------------------------
// Main GEMM pure fp16 1-term, FULL K, direct epilogue.
// 144 CTAs x 256 threads, occ 2 (48 KB smem, ~90 regs). 32 stages of 64.
// out[n,c] = fp16(x[n,:]) . fp16(M[c,:]) + beta[c], permuted [F,P]->[P,F].
// ---------------------------------------------------------------------------
__global__ void __launch_bounds__(256, 2)
main_mma(const float* __restrict__ x, float* __restrict__ out)
{
    extern __shared__ char smraw[];
    const u32 base = (smem_u32(smraw) + 1023u) & ~1023u;
    const u32 XH[2] = { base,          base + 16384u };
    const u32 BH[2] = { base + 32768u, base + 40960u };

    const int tid = threadIdx.x;
    const int wid = tid >> 5, lane = tid & 31;
    const int n0 = blockIdx.x * 128;
    const int m0 = wid * 16;

    float acc[8][4];
#pragma unroll
    for (int i = 0; i < 8; ++i)
#pragma unroll
        for (int j = 0; j < 4; ++j) acc[i][j] = 0.f;

    const int xr = tid >> 4, xc4 = tid & 15;

    float4 ra[8];
#pragma unroll
    for (int i = 0; i < 8; ++i)
        ra[i] = *(const float4*)(x + (size_t)(n0 + xr + 16 * i) * EE + xc4 * 4);
    {
        const char* sh = (const char*)g_Bh + (size_t)tid * 32;
        cp16(BH[0] + (u32)tid * 32,      sh);
        cp16(BH[0] + (u32)tid * 32 + 16, sh + 16);
        cp_commit();
    }

    for (int t = 0; t < 32; ++t) {
        const int buf = t & 1;
        cp_wait0();

        // convert X chunk t -> fp16, store swizzled
#pragma unroll
        for (int i = 0; i < 8; ++i) {
            const u32 sw = swz((u32)((xr + 16 * i) * 128 + xc4 * 8));
            float4 v = ra[i];
            __half2 H01 = __floats2half2_rn(v.x, v.y);
            __half2 H23 = __floats2half2_rn(v.z, v.w);
            sts64(sw + XH[buf], *(u32*)&H01, *(u32*)&H23);
        }
        __syncthreads();

        if (t + 1 < 32) {
            const char* sh = (const char*)g_Bh + (size_t)(t + 1) * 8192 + tid * 32;
            cp16(BH[buf ^ 1] + (u32)tid * 32,      sh);
            cp16(BH[buf ^ 1] + (u32)tid * 32 + 16, sh + 16);
            cp_commit();
            const int k0 = (t + 1) * KS;
#pragma unroll
            for (int i = 0; i < 8; ++i)
                ra[i] = *(const float4*)(x + (size_t)(n0 + xr + 16 * i) * EE + k0 + xc4 * 4);
        }

#pragma unroll
        for (int s = 0; s < 4; ++s) {
            const u32 xo = swz((u32)((m0 + (lane & 15)) * 128 + s * 32 + (lane >> 4) * 16));
            u32 a0, a1, a2, a3;
            ldsm4(a0, a1, a2, a3, XH[buf] + xo);
#pragma unroll
            for (int j = 0; j < 4; ++j) {
                const u32 bo_ = swz((u32)((16 * j + (lane & 15)) * 128 + s * 32 + (lane >> 4) * 16));
                u32 b0, b1, b2, b3;
                ldsm4(b0, b1, b2, b3, BH[buf] + bo_);
                mma16816h(acc[2 * j],     a0, a1, a2, a3, b0, b2);
                mma16816h(acc[2 * j + 1], a0, a1, a2, a3, b1, b3);
            }
        }
    }

    // Epilogue: permuted store [F,P]->[P,F], + beta
    const int r0 = lane >> 2;
    const int cb = 2 * (lane & 3);
    const int na = n0 + m0 + r0;
    const int nb2 = na + 8;
    const int pa = na & 1023, ta = na >> 10;
    const int pb2 = nb2 & 1023, tb = nb2 >> 10;
    float* oa = out + (size_t)pa * (FF * CC) + ta * CC;
    float* ob = out + (size_t)pb2 * (FF * CC) + tb * CC;
#pragma unroll
    for (int nt = 0; nt < 8; ++nt) {
        const int c = 8 * nt + cb;
        const float2 b = *(const float2*)&g_beta[c];
        float2 w0, w1;
        w0.x = acc[nt][0] + b.x; w0.y = acc[nt][1] + b.y;
        w1.x = acc[nt][2] + b.x; w1.y = acc[nt][3] + b.y;
        *(float2*)(oa + c) = w0;
        *(float2*)(ob + c) = w1;
    }
}

// ---------------------------------------------------------------------------
extern "C" void kernel_launch(void* const* d_in, const int* in_sizes, int n_in,
                              void* d_out, int out_size)
{
    (void)in_sizes; (void)n_in; (void)out_size;
    const float* emb = (const float*)d_in[0];
    const float* Wv  = (const float*)d_in[3];
    const float* bv  = (const float*)d_in[6];
    const float* Wo  = (const float*)d_in[7];
    const float* bo  = (const float*)d_in[8];
    const float* Wmp = (const float*)d_in[9];
    const float* bmp = (const float*)d_in[10];
    float* out = (float*)d_out;

    const int wg_smem = 65536 + 1024;
    const int mm_smem = 49152 + 1024;
    cudaFuncSetAttribute(wgemm, cudaFuncAttributeMaxDynamicSharedMemorySize, wg_smem);
    cudaFuncSetAttribute(main_mma, cudaFuncAttributeMaxDynamicSharedMemorySize, mm_smem);

    // T1 = Wmp @ Wo (split-K over full chip), reduce
    wgemm<<<dim3(32, KCH), 256, wg_smem>>>(Wmp, Wo, 0);
    reduceK<<<128, 256>>>(0, nullptr, nullptr, nullptr, nullptr);
    // M = 0.75 * T1 @ Wv; reduce + fp16 quantize/swizzle + beta (fused)
    wgemm<<<dim3(32, KCH), 256, wg_smem>>>(nullptr, Wv, 1);
    reduceK<<<192, 256>>>(1, bv, bo, bmp, Wmp);

    // Main GEMM pure fp16 1-term, full K, direct permuted epilogue + beta
    main_mma<<<144, 256, mm_smem>>>(emb, out);
}

// round 17
// speedup vs baseline: 1.2323x; 1.2323x over previous
#include <cuda_runtime.h>
#include <cuda_bf16.h>
#include <cuda_fp16.h>
#include <cstdint>

#define EE   2048
#define CC   64
#define FF   18
#define NTOK 18432
#define KS   64
#define KCH  8       // split-K chunks in wgemm

typedef unsigned long long u64;
typedef unsigned int u32;

// Scratch (__device__ globals: allocation-free rule)
__device__ float g_part[KCH * CC * EE];                   // wgemm split-K partials (4 MB)
__device__ float g_mpart[2 * NTOK * CC];                  // main split-K partials (9.4 MB)
__device__ float g_T1[CC * EE];                           // Wmp @ Wo
__device__ __align__(16) float g_beta[CC];
__device__ __align__(16) unsigned char g_Bh[CC * EE * 2]; // M (fp16), pre-swizzled tiles
__device__ int g_cnt[64];                                 // per-tile arrival counters
                                                          // (zero-init; self-resetting)

// ---------------- helpers ----------------
__device__ __forceinline__ unsigned smem_u32(const void* p) {
    return (unsigned)__cvta_generic_to_shared(p);
}
__device__ __forceinline__ void cp16(unsigned s, const void* g) {
    asm volatile("cp.async.ca.shared.global [%0], [%1], 16;" :: "r"(s), "l"(g));
}
__device__ __forceinline__ void cp_commit() { asm volatile("cp.async.commit_group;"); }
__device__ __forceinline__ void cp_wait0()  { asm volatile("cp.async.wait_group 0;"); }
__device__ __forceinline__ void sts64(u32 a, u32 lo, u32 hi) {
    asm volatile("st.shared.v2.u32 [%0], {%1,%2};" :: "r"(a), "r"(hi), "r"(lo));
}
__device__ __forceinline__ void ldsm4(u32& r0, u32& r1, u32& r2, u32& r3, u32 a) {
    asm volatile("ldmatrix.sync.aligned.m8n8.x4.shared.b16 {%0,%1,%2,%3}, [%4];"
                 : "=r"(r0), "=r"(r1), "=r"(r2), "=r"(r3) : "r"(a));
}
__device__ __forceinline__ void ldsm4t(u32& r0, u32& r1, u32& r2, u32& r3, u32 a) {
    asm volatile("ldmatrix.sync.aligned.m8n8.x4.trans.shared.b16 {%0,%1,%2,%3}, [%4];"
                 : "=r"(r0), "=r"(r1), "=r"(r2), "=r"(r3) : "r"(a));
}
__device__ __forceinline__ void mma16816(float* c, u32 a0, u32 a1, u32 a2, u32 a3,
                                         u32 b0, u32 b1) {
    asm volatile("mma.sync.aligned.m16n8k16.row.col.f32.bf16.bf16.f32 "
                 "{%0,%1,%2,%3}, {%4,%5,%6,%7}, {%8,%9}, {%0,%1,%2,%3};"
                 : "+f"(c[0]), "+f"(c[1]), "+f"(c[2]), "+f"(c[3])
                 : "r"(a0), "r"(a1), "r"(a2), "r"(a3), "r"(b0), "r"(b1));
}
__device__ __forceinline__ void mma16816h(float* c, u32 a0, u32 a1, u32 a2, u32 a3,
                                          u32 b0, u32 b1) {
    asm volatile("mma.sync.aligned.m16n8k16.row.col.f32.f16.f16.f32 "
                 "{%0,%1,%2,%3}, {%4,%5,%6,%7}, {%8,%9}, {%0,%1,%2,%3};"
                 : "+f"(c[0]), "+f"(c[1]), "+f"(c[2]), "+f"(c[3])
                 : "r"(a0), "r"(a1), "r"(a2), "r"(a3), "r"(b0), "r"(b1));
}
__device__ __forceinline__ u32 swz(u32 off) { return off ^ ((off >> 3) & 0x70u); }

__device__ __forceinline__ void split4(float4 v, u32& h01, u32& h23, u32& l01, u32& l23) {
    asm("cvt.rn.bf16x2.f32 %0, %1, %2;" : "=r"(h01) : "f"(v.y), "f"(v.x));
    asm("cvt.rn.bf16x2.f32 %0, %1, %2;" : "=r"(h23) : "f"(v.w), "f"(v.z));
    float e0 = v.x - __uint_as_float(h01 << 16);
    float e1 = v.y - __uint_as_float(h01 & 0xffff0000u);
    float e2 = v.z - __uint_as_float(h23 << 16);
    float e3 = v.w - __uint_as_float(h23 & 0xffff0000u);
    asm("cvt.rn.bf16x2.f32 %0, %1, %2;" : "=r"(l01) : "f"(e1), "f"(e0));
    asm("cvt.rn.bf16x2.f32 %0, %1, %2;" : "=r"(l23) : "f"(e3), "f"(e2));
}

// ---------------------------------------------------------------------------
// wgemm (split-K + FUSED last-block reduction):
//   partial[kc][c][j] = sum_{k in chunk kc} A[c,k] * B[k,j]
//   last CTA per j-tile sums the 8 partials (fixed order -> deterministic):
//     mode 0 -> g_T1 fp32;  mode 1 -> 0.75x fp16, pre-swizzled into g_Bh.
// Mode 1 extra blocks (blockIdx.x in [32,96), y==0):
//     beta[c] = 0.75*(T1[c,:]@bv + Wmp[c,:]@bo) + bmp[c]
// Counters self-reset -> graph-replay-safe.
// ---------------------------------------------------------------------------
__global__ void __launch_bounds__(256, 2)
wgemm(const float* __restrict__ Aglob, const float* __restrict__ Bglob, int mode,
      const float* __restrict__ bv, const float* __restrict__ bo,
      const float* __restrict__ bmp, const float* __restrict__ WmpB)
{
    const int tid = threadIdx.x;

    if (blockIdx.x >= 32) {            // beta blocks (mode 1 only, y==0)
        if (blockIdx.y != 0) return;
        __shared__ float red[256];
        const int c = blockIdx.x - 32;
        const float4* t1r = (const float4*)(g_T1 + (size_t)c * EE);
        const float4* wmr = (const float4*)(WmpB + (size_t)c * EE);
        const float4* bv4 = (const float4*)bv;
        const float4* bo4 = (const float4*)bo;
        float s = 0.f;
#pragma unroll
        for (int q = 0; q < 2; ++q) {
            const int i = tid + 256 * q;
            float4 a = t1r[i], b = bv4[i], d = wmr[i], e = bo4[i];
            s += a.x * b.x + a.y * b.y + a.z * b.z + a.w * b.w;
            s += d.x * e.x + d.y * e.y + d.z * e.z + d.w * e.w;
        }
        red[tid] = s;
        __syncthreads();
#pragma unroll
        for (int o = 128; o >= 32; o >>= 1) {
            if (tid < o) red[tid] += red[tid + o];
            __syncthreads();
        }
        if (tid < 32) {
            float v = red[tid];
#pragma unroll
            for (int o = 16; o; o >>= 1) v += __shfl_xor_sync(0xffffffffu, v, o);
            if (tid == 0) g_beta[c] = 0.75f * v + bmp[c];
        }
        return;
    }

    const float* A = mode ? g_T1 : Aglob;
    extern __shared__ char smraw[];
    const u32 base = (smem_u32(smraw) + 1023u) & ~1023u;
    const u32 AH[2]  = { base,          base + 8192u  };
    const u32 AL[2]  = { base + 16384u, base + 24576u };
    const u32 BSH[2] = { base + 32768u, base + 40960u };
    const u32 BSL[2] = { base + 49152u, base + 57344u };

    const int wid = tid >> 5, lane = tid & 31;
    const int j0 = blockIdx.x * 64;
    const int kbase = blockIdx.y * 256;
    const int c0 = (wid & 3) * 16;
    const int jh = (wid >> 2) * 32;

    const int lr = tid >> 4;
    const int lc = tid & 15;

    float acc[4][4];
#pragma unroll
    for (int i = 0; i < 4; ++i)
#pragma unroll
        for (int j = 0; j < 4; ++j) acc[i][j] = 0.f;

    float4 rA[4], rB[4];
#pragma unroll
    for (int i = 0; i < 4; ++i) {
        rA[i] = *(const float4*)(A + (size_t)(lr + 16 * i) * EE + kbase + lc * 4);
        rB[i] = *(const float4*)(Bglob + (size_t)(kbase + lr + 16 * i) * EE + j0 + lc * 4);
    }

    for (int t = 0; t < 4; ++t) {
        const int buf = t & 1;
#pragma unroll
        for (int i = 0; i < 4; ++i) {
            const u32 sw = swz((u32)((lr + 16 * i) * 128 + lc * 8));
            u32 h01, h23, l01, l23;
            split4(rA[i], h01, h23, l01, l23);
            // NOTE sts64 argument order fixed relative to helper (lo, hi)
            asm volatile("st.shared.v2.u32 [%0], {%1,%2};" :: "r"(AH[buf] + sw), "r"(h01), "r"(h23));
            asm volatile("st.shared.v2.u32 [%0], {%1,%2};" :: "r"(AL[buf] + sw), "r"(l01), "r"(l23));
            split4(rB[i], h01, h23, l01, l23);
            asm volatile("st.shared.v2.u32 [%0], {%1,%2};" :: "r"(BSH[buf] + sw), "r"(h01), "r"(h23));
            asm volatile("st.shared.v2.u32 [%0], {%1,%2};" :: "r"(BSL[buf] + sw), "r"(l01), "r"(l23));
        }
        __syncthreads();

        if (t + 1 < 4) {
            const int kc = kbase + (t + 1) * 64;
#pragma unroll
            for (int i = 0; i < 4; ++i) {
                rA[i] = *(const float4*)(A + (size_t)(lr + 16 * i) * EE + kc + lc * 4);
                rB[i] = *(const float4*)(Bglob + (size_t)(kc + lr + 16 * i) * EE + j0 + lc * 4);
            }
        }

        const int r = lane & 7, g = lane >> 3;
#pragma unroll
        for (int s = 0; s < 4; ++s) {
            const u32 asw = swz((u32)((c0 + (lane & 15)) * 128 + s * 32 + (lane >> 4) * 16));
            u32 a0, a1, a2, a3, f0, f1, f2, f3;
            ldsm4(a0, a1, a2, a3, AH[buf] + asw);
            ldsm4(f0, f1, f2, f3, AL[buf] + asw);
#pragma unroll
            for (int h = 0; h < 2; ++h) {
                const int jb = jh + h * 16;
                const u32 bsw = swz((u32)((s * 16 + (g >> 1) * 8 + r) * 128
                                          + (jb + (g & 1) * 8) * 2));
                u32 b0, b1, b2, b3, e0, e1, e2, e3;
                ldsm4t(b0, b1, b2, b3, BSH[buf] + bsw);
                ldsm4t(e0, e1, e2, e3, BSL[buf] + bsw);
                mma16816(acc[2 * h],     a0, a1, a2, a3, b0, b2);
                mma16816(acc[2 * h],     a0, a1, a2, a3, e0, e2);
                mma16816(acc[2 * h],     f0, f1, f2, f3, b0, b2);
                mma16816(acc[2 * h + 1], a0, a1, a2, a3, b1, b3);
                mma16816(acc[2 * h + 1], a0, a1, a2, a3, e1, e3);
                mma16816(acc[2 * h + 1], f0, f1, f2, f3, b1, b3);
            }
        }
        if (t + 1 < 4) __syncthreads();
    }

    // write partials
    {
        const int r0 = lane >> 2;
        const int cb = 2 * (lane & 3);
        float* pbase = g_part + (size_t)blockIdx.y * (CC * EE);
#pragma unroll
        for (int nt = 0; nt < 4; ++nt) {
            const int j = j0 + jh + nt * 8 + cb;
            const int ca = c0 + r0, cbig = ca + 8;
            *(float2*)&pbase[(size_t)ca * EE + j]   = make_float2(acc[nt][0], acc[nt][1]);
            *(float2*)&pbase[(size_t)cbig * EE + j] = make_float2(acc[nt][2], acc[nt][3]);
        }
    }

    // last-arriver reduction for this j-tile
    __threadfence();
    __shared__ int amlast;
    if (tid == 0) {
        const int old = atomicAdd(&g_cnt[mode * 32 + blockIdx.x], 1);
        amlast = (old == KCH - 1) ? 1 : 0;
    }
    __syncthreads();
    if (amlast) {
        __threadfence();   // acquire: other CTAs' partials now visible
#pragma unroll
        for (int q = 0; q < 4; ++q) {
            const int e4 = tid + 256 * q;        // 0..1023 float4 groups in tile
            const int c = e4 >> 4;               // 0..63
            const int j = j0 + (e4 & 15) * 4;    // global j
            float4 s = make_float4(0.f, 0.f, 0.f, 0.f);
#pragma unroll
            for (int kc = 0; kc < KCH; ++kc) {
                float4 v = *(const float4*)&g_part[(size_t)kc * (CC * EE) + (size_t)c * EE + j];
                s.x += v.x; s.y += v.y; s.z += v.z; s.w += v.w;
            }
            if (mode == 0) {
                *(float4*)&g_T1[(size_t)c * EE + j] = s;
            } else {
                s.x *= 0.75f; s.y *= 0.75f; s.z *= 0.75f; s.w *= 0.75f;
                __half2 H01 = __floats2half2_rn(s.x, s.y);
                __half2 H23 = __floats2half2_rn(s.z, s.w);
                const int stage = j >> 6, kk = j & 63;
                const u32 sw = swz((u32)(c * 128 + kk * 2));
                *(u32*)(g_Bh + (size_t)stage * 8192 + sw)     = *(u32*)&H01;
                *(u32*)(g_Bh + (size_t)stage * 8192 + sw + 4) = *(u32*)&H23;
            }
        }
        if (tid == 0) g_cnt[mode * 32 + blockIdx.x] = 0;   // self-reset (replay-safe)
    }
}

// ---------------------------------------------------------------------------
// Main GEMM pure fp16 1-term split-K: grid (144, 2) = 288 CTAs (2/SM — the
// resident-partner is load-bearing, rounds 10/16 proved it). Round-15 champion.
// ---------------------------------------------------------------------------
__global__ void __launch_bounds__(256, 2)
main_mma_sk(const float* __restrict__ x)
{
    extern __shared__ char smraw[];
    const u32 base = (smem_u32(smraw) + 1023u) & ~1023u;
    const u32 XH[2] = { base,          base + 16384u };
    const u32 BH[2] = { base + 32768u, base + 40960u };

    const int tid = threadIdx.x;
    const int wid = tid >> 5, lane = tid & 31;
    const int n0 = blockIdx.x * 128;
    const int kh = blockIdx.y;
    const int kbase = kh * 1024;
    const int m0 = wid * 16;

    float acc[8][4];
#pragma unroll
    for (int i = 0; i < 8; ++i)
#pragma unroll
        for (int j = 0; j < 4; ++j) acc[i][j] = 0.f;

    const int xr = tid >> 4, xc4 = tid & 15;

    float4 ra[8];
#pragma unroll
    for (int i = 0; i < 8; ++i)
        ra[i] = *(const float4*)(x + (size_t)(n0 + xr + 16 * i) * EE + kbase + xc4 * 4);
    {
        const char* sh = (const char*)g_Bh + (size_t)(kh * 16) * 8192 + tid * 32;
        cp16(BH[0] + (u32)tid * 32,      sh);
        cp16(BH[0] + (u32)tid * 32 + 16, sh + 16);
        cp_commit();
    }

    for (int t = 0; t < 16; ++t) {
        const int buf = t & 1;
        cp_wait0();

#pragma unroll
        for (int i = 0; i < 8; ++i) {
            const u32 sw = swz((u32)((xr + 16 * i) * 128 + xc4 * 8));
            float4 v = ra[i];
            __half2 H01 = __floats2half2_rn(v.x, v.y);
            __half2 H23 = __floats2half2_rn(v.z, v.w);
            asm volatile("st.shared.v2.u32 [%0], {%1,%2};"
                         :: "r"(XH[buf] + sw), "r"(*(u32*)&H01), "r"(*(u32*)&H23));
        }
        __syncthreads();

        if (t + 1 < 16) {
            const char* sh = (const char*)g_Bh + (size_t)(kh * 16 + t + 1) * 8192 + tid * 32;
            cp16(BH[buf ^ 1] + (u32)tid * 32,      sh);
            cp16(BH[buf ^ 1] + (u32)tid * 32 + 16, sh + 16);
            cp_commit();
            const int k0 = kbase + (t + 1) * KS;
#pragma unroll
            for (int i = 0; i < 8; ++i)
                ra[i] = *(const float4*)(x + (size_t)(n0 + xr + 16 * i) * EE + k0 + xc4 * 4);
        }

#pragma unroll
        for (int s = 0; s < 4; ++s) {
            const u32 xo = swz((u32)((m0 + (lane & 15)) * 128 + s * 32 + (lane >> 4) * 16));
            u32 a0, a1, a2, a3;
            ldsm4(a0, a1, a2, a3, XH[buf] + xo);
#pragma unroll
            for (int j = 0; j < 4; ++j) {
                const u32 bo_ = swz((u32)((16 * j + (lane & 15)) * 128 + s * 32 + (lane >> 4) * 16));
                u32 b0, b1, b2, b3;
                ldsm4(b0, b1, b2, b3, BH[buf] + bo_);
                mma16816h(acc[2 * j],     a0, a1, a2, a3, b0, b2);
                mma16816h(acc[2 * j + 1], a0, a1, a2, a3, b1, b3);
            }
        }
    }

    const int r0 = lane >> 2;
    const int cb = 2 * (lane & 3);
    const int na = n0 + m0 + r0;
    float* pa = g_mpart + ((size_t)kh * NTOK + na) * CC;
    float* pb = pa + 8 * CC;
#pragma unroll
    for (int nt = 0; nt < 8; ++nt) {
        const int c = 8 * nt + cb;
        *(float2*)(pa + c) = make_float2(acc[nt][0], acc[nt][1]);
        *(float2*)(pb + c) = make_float2(acc[nt][2], acc[nt][3]);
    }
}

// ---------------------------------------------------------------------------
// Combine (float4): out[p, t, c..c+3] = part0 + part1 + beta,  n = t*1024+p
// ---------------------------------------------------------------------------
__global__ void combine(float* __restrict__ out)
{
    const int e4 = blockIdx.x * 256 + threadIdx.x;   // 0 .. NTOK*CC/4-1
    const int n = e4 >> 4, c = (e4 & 15) * 4;
    const float4 a = *(const float4*)&g_mpart[(size_t)n * CC + c];
    const float4 b = *(const float4*)&g_mpart[(size_t)(NTOK + n) * CC + c];
    const float4 bb = *(const float4*)&g_beta[c];
    float4 w;
    w.x = a.x + b.x + bb.x; w.y = a.y + b.y + bb.y;
    w.z = a.z + b.z + bb.z; w.w = a.w + b.w + bb.w;
    const int p = n & 1023, t = n >> 10;
    *(float4*)&out[(size_t)p * (FF * CC) + t * CC + c] = w;
}

// ---------------------------------------------------------------------------
extern "C" void kernel_launch(void* const* d_in, const int* in_sizes, int n_in,
                              void* d_out, int out_size)
{
    (void)in_sizes; (void)n_in; (void)out_size;
    const float* emb = (const float*)d_in[0];
    const float* Wv  = (const float*)d_in[3];
    const float* bv  = (const float*)d_in[6];
    const float* Wo  = (const float*)d_in[7];
    const float* bo  = (const float*)d_in[8];
    const float* Wmp = (const float*)d_in[9];
    const float* bmp = (const float*)d_in[10];
    float* out = (float*)d_out;

    const int wg_smem = 65536 + 1024;
    const int mm_smem = 49152 + 1024;
    cudaFuncSetAttribute(wgemm, cudaFuncAttributeMaxDynamicSharedMemorySize, wg_smem);
    cudaFuncSetAttribute(main_mma_sk, cudaFuncAttributeMaxDynamicSharedMemorySize, mm_smem);

    // T1 = Wmp @ Wo (split-K + fused last-block reduce -> g_T1)
    wgemm<<<dim3(32, KCH), 256, wg_smem>>>(Wmp, Wo, 0, nullptr, nullptr, nullptr, nullptr);
    // M = 0.75 * T1 @ Wv (fused reduce -> fp16 swizzled g_Bh) + beta blocks
    wgemm<<<dim3(96, KCH), 256, wg_smem>>>(nullptr, Wv, 1, bv, bo, bmp, Wmp);

    // Main GEMM pure fp16 1-term split-K (288 CTAs = 2/SM) + combine epilogue
    main_mma_sk<<<dim3(144, 2), 256, mm_smem>>>(emb);
    combine<<<(NTOK * CC) / 4 / 256, 256>>>(out);
}